// round 16
// baseline (speedup 1.0000x reference)
#include <cuda_runtime.h>
#include <cuda_bf16.h>
#include <cuda_fp8.h>
#include <cstdint>

// ---------------- problem constants ----------------
#define BATCH   8
#define N_ANCH  2784
#define NK      2783
#define DFEAT   704
#define DCAT    1408
#define FH      11
#define FW      20
#define CB      512
#define CF      64
#define OUTW    77
#define RCOLS   75

// fp8 scales (powers of 2, exact)
#define SC_BAF   16.0f
#define SC_W     64.0f
#define INV_G1   (1.0f / (SC_BAF * SC_W))    // 1/1024
#define SC_P     256.0f                       // E storage scale
#define SC_Z     4096.0f                      // Z storage scale
#define INV_Z    (1.0f / SC_Z)                // 1/4096

// ---------------- scratch (device globals) ----------------
__device__ float g_feat[(size_t)BATCH * CF * FH * FW];
__device__ __nv_bfloat16 g_baf [(size_t)BATCH * N_ANCH * DFEAT];   // bf16 gathered
__device__ unsigned char g_baf8[(size_t)BATCH * N_ANCH * DFEAT];   // fp8 baf*16
__device__ unsigned char g_w8  [(size_t)NK * DFEAT];               // fp8 attn_w*64
__device__ unsigned char g_s8  [(size_t)BATCH * N_ANCH * N_ANCH];  // fp8 E=exp(score)*256, m-layout, diag=0
__device__ float         g_sum [(size_t)BATCH * N_ANCH];           // rowsum(exp)*256 (atomic)
__device__ __nv_bfloat16 g_wZU [(size_t)160 * DFEAT];              // [W3a(80); W3b(80)] rows x 704
__device__ unsigned char g_Zt8 [(size_t)BATCH * 80 * N_ANCH];      // fp8 Z^T * 4096
__device__ __nv_bfloat16 g_U   [(size_t)BATCH * N_ANCH * 80];      // U row-major bf16

// ---------------- helpers ----------------
__device__ __forceinline__ uint32_t sptr(const void* p) {
    return (uint32_t)__cvta_generic_to_shared(p);
}
__device__ __forceinline__ void cpa16(uint32_t dst, const void* src, bool ok) {
    int sz = ok ? 16 : 0;
    asm volatile("cp.async.cg.shared.global [%0], [%1], 16, %2;\n"
                 :: "r"(dst), "l"(src), "r"(sz));
}
__device__ __forceinline__ void cp_commit() { asm volatile("cp.async.commit_group;\n"); }
__device__ __forceinline__ void ldsm4(uint32_t* r, uint32_t a) {
    asm volatile("ldmatrix.sync.aligned.m8n8.x4.shared.b16 {%0,%1,%2,%3}, [%4];"
                 : "=r"(r[0]), "=r"(r[1]), "=r"(r[2]), "=r"(r[3]) : "r"(a));
}
__device__ __forceinline__ void mma16816(float* c, const uint32_t* a, uint32_t b0, uint32_t b1) {
    asm volatile("mma.sync.aligned.m16n8k16.row.col.f32.bf16.bf16.f32 "
                 "{%0,%1,%2,%3}, {%4,%5,%6,%7}, {%8,%9}, {%0,%1,%2,%3};"
                 : "+f"(c[0]), "+f"(c[1]), "+f"(c[2]), "+f"(c[3])
                 : "r"(a[0]), "r"(a[1]), "r"(a[2]), "r"(a[3]), "r"(b0), "r"(b1));
}
__device__ __forceinline__ void mma16832(float* c, const uint32_t* a, uint32_t b0, uint32_t b1) {
    asm volatile("mma.sync.aligned.m16n8k32.row.col.f32.e4m3.e4m3.f32 "
                 "{%0,%1,%2,%3}, {%4,%5,%6,%7}, {%8,%9}, {%0,%1,%2,%3};"
                 : "+f"(c[0]), "+f"(c[1]), "+f"(c[2]), "+f"(c[3])
                 : "r"(a[0]), "r"(a[1]), "r"(a[2]), "r"(a[3]), "r"(b0), "r"(b1));
}
__device__ __forceinline__ __nv_bfloat162 pack2(float a, float b) {
    return __floats2bfloat162_rn(a, b);
}
__device__ __forceinline__ unsigned char to_fp8(float v) {
    return (unsigned char)__nv_cvt_float_to_fp8(v, __NV_SATFINITE, __NV_E4M3);
}
__device__ __forceinline__ float fp8_to_f(unsigned char c) {
    __half_raw h = __nv_cvt_fp8_to_halfraw(c, __NV_E4M3);
    return __half2float(*(__half*)&h);
}

// ---------------- K0: zero rowsum accumulator ----------------
__global__ __launch_bounds__(256) void k_zero() {
    int i = blockIdx.x * 256 + threadIdx.x;
    if (i < BATCH * N_ANCH) g_sum[i] = 0.f;
}

// ---------------- K1: 1x1 conv ----------------
__global__ __launch_bounds__(64) void k_feat(const float* __restrict__ x,
                                             const float* __restrict__ w,
                                             const float* __restrict__ bias) {
    int p = blockIdx.x;
    int wpos = p % FW;
    int h = (p / FW) % FH;
    int b = p / (FW * FH);
    __shared__ float xv[CB];
    const float* xp = x + ((size_t)b * CB) * (FH * FW) + h * FW + wpos;
    for (int c = threadIdx.x; c < CB; c += 64) xv[c] = xp[(size_t)c * (FH * FW)];
    __syncthreads();
    int o = threadIdx.x;
    const float* wr = w + (size_t)o * CB;
    float acc = bias[o];
#pragma unroll 8
    for (int c = 0; c < CB; c++) acc += wr[c] * xv[c];
    g_feat[(((size_t)b * CF + o) * FH + h) * FW + wpos] = acc;
}

// ---------------- K2: gather baf -> bf16 + fp8 ----------------
__global__ __launch_bounds__(128) void k_gather(const int* __restrict__ cut_xs,
                                                const unsigned char* __restrict__ invalid) {
    int n = blockIdx.x, b = blockIdx.y;
    __shared__ int xs[FH];
    __shared__ unsigned char inv[FH];
    if (threadIdx.x < FH) {
        xs[threadIdx.x]  = cut_xs[n * FH + threadIdx.x];
        inv[threadIdx.x] = invalid[n * FH + threadIdx.x];
    }
    __syncthreads();
    size_t base = ((size_t)(b * N_ANCH + n)) * DFEAT;
    __nv_bfloat16* dst = g_baf + base;
    unsigned char* dst8 = g_baf8 + base;
    const float* fb = g_feat + (size_t)b * CF * FH * FW;
    for (int d = threadIdx.x; d < DFEAT; d += 128) {
        int c = d / FH, h = d - c * FH;
        float v = inv[h] ? 0.0f : fb[(c * FH + h) * FW + xs[h]];
        dst[d] = __float2bfloat16(v);
        dst8[d] = to_fp8(v * SC_BAF);
    }
}

// ---------------- K2b: attn_w -> fp8 *64 ----------------
__global__ __launch_bounds__(256) void k_convw(const float* __restrict__ w) {
    size_t i = (size_t)blockIdx.x * 256 + threadIdx.x;
    if (i < (size_t)NK * DFEAT) g_w8[i] = to_fp8(w[i] * SC_W);
}

// ---------------- K2c: split heads W into [W3a; W3b] rows x 704 (bf16) ----------------
__global__ __launch_bounds__(256) void k_convwzu(const float* __restrict__ cls_w,
                                                 const float* __restrict__ reg_w) {
    int i = blockIdx.x * 256 + threadIdx.x;
    if (i < 160 * DFEAT) {
        int row = i / DFEAT, k = i - row * DFEAT;
        int o = (row < 80) ? row : row - 80;
        int kc = (row < 80) ? k : k + DFEAT;
        float v = 0.f;
        if (o < 2)          v = cls_w[(size_t)o * DCAT + kc];
        else if (o < RCOLS) v = reg_w[(size_t)(o - 2) * DCAT + kc];
        g_wZU[i] = __float2bfloat16(v);
    }
}

// =================================================================
// GEMM1 (fp8): E = fp8(exp(score)*256) diag-skip layout + fused rowsum
// =================================================================
#define NSTG 3
#define STG 10240u
#define SMEM1_TOT (NSTG * 2 * STG)   // 61440

__global__ __launch_bounds__(256, 2) void k_gemm1_fp8(const float* __restrict__ bias, int bz0) {
    const int Kvalid = DFEAT;
    const int S = (Kvalid + 63) / 64;   // 11
    int bz = bz0 + blockIdx.z;
    int m0 = blockIdx.y * 128;
    int n0 = blockIdx.x * 128;
    const unsigned char* A = g_baf8 + (size_t)bz * N_ANCH * DFEAT;
    const unsigned char* B = g_w8;
    unsigned char* C = g_s8 + (size_t)bz * N_ANCH * N_ANCH;
    float* Srow = g_sum + (size_t)bz * N_ANCH;

    extern __shared__ __align__(16) char smem[];
    uint32_t sbA = sptr(smem);
    uint32_t sbB = sbA + NSTG * STG;

    int tid = threadIdx.x, lane = tid & 31, warp = tid >> 5;
    int wm = (warp >> 1) * 32, wn = (warp & 1) * 64;
    float c[2][8][4] = {};

    auto load_stage = [&](int s, int buf) {
        int ks = s * 64;
        uint32_t baA = sbA + buf * STG;
        uint32_t baB = sbB + buf * STG;
#pragma unroll
        for (int i = 0; i < 2; i++) {
            int idx = tid + i * 256;
            int row = idx >> 2, ch = idx & 3;
            int koff = ks + ch * 16;
            bool okk = koff < Kvalid;
            int gm = m0 + row;
            bool okA = okk && (gm < N_ANCH);
            cpa16(baA + (uint32_t)row * 80u + (uint32_t)ch * 16u,
                  A + (size_t)(okA ? gm : 0) * DFEAT + (okk ? koff : 0), okA);
            int gn = n0 + row;
            bool okB = okk && (gn < NK);
            cpa16(baB + (uint32_t)row * 80u + (uint32_t)ch * 16u,
                  B + (size_t)(okB ? gn : 0) * DFEAT + (okk ? koff : 0), okB);
        }
    };

#pragma unroll
    for (int s = 0; s < NSTG - 1; s++) { if (s < S) load_stage(s, s); cp_commit(); }

    int lr = lane & 15;
    uint32_t lcb = (uint32_t)(lane >> 4) * 16u;
    uint32_t aoff[2], boff[4];
#pragma unroll
    for (int mi = 0; mi < 2; mi++) aoff[mi] = (uint32_t)(wm + mi * 16 + lr) * 80u + lcb;
#pragma unroll
    for (int nj = 0; nj < 4; nj++) boff[nj] = (uint32_t)(wn + nj * 16 + lr) * 80u + lcb;

    for (int s = 0; s < S; s++) {
        asm volatile("cp.async.wait_group %0;" :: "n"(NSTG - 2) : "memory");
        __syncthreads();
        int st = s % NSTG;
        uint32_t aA = sbA + (uint32_t)st * STG;
        uint32_t aB = sbB + (uint32_t)st * STG;
#pragma unroll
        for (int h = 0; h < 2; h++) {
            uint32_t cb = (uint32_t)h * 32u;
            uint32_t a[2][4], bb[4][4];
#pragma unroll
            for (int mi = 0; mi < 2; mi++) ldsm4(a[mi], aA + aoff[mi] + cb);
#pragma unroll
            for (int nj = 0; nj < 4; nj++) ldsm4(bb[nj], aB + boff[nj] + cb);
#pragma unroll
            for (int mi = 0; mi < 2; mi++)
#pragma unroll
                for (int nj = 0; nj < 4; nj++) {
                    mma16832(c[mi][nj * 2 + 0], a[mi], bb[nj][0], bb[nj][2]);
                    mma16832(c[mi][nj * 2 + 1], a[mi], bb[nj][1], bb[nj][3]);
                }
        }
        __syncthreads();
        int t = s + NSTG - 1;
        if (t < S) load_stage(t, t % NSTG);
        cp_commit();
    }

    float rsum[2][2] = {};
    auto put = [&](int r, int k, float acc, float& rs) {
        if (r >= N_ANCH || k >= NK) return;
        float score = acc * INV_G1 + __ldg(&bias[k]);
        float ex = __expf(score) * SC_P;
        rs += ex;
        int m = k + (k >= r);
        C[(size_t)r * N_ANCH + m] = to_fp8(ex);
        if (k == r) C[(size_t)r * N_ANCH + r] = 0;
        if (r == NK && k == NK - 1) C[(size_t)r * N_ANCH + NK] = 0;
    };
#pragma unroll
    for (int mi = 0; mi < 2; mi++)
#pragma unroll
        for (int nj = 0; nj < 4; nj++)
#pragma unroll
            for (int jj = 0; jj < 2; jj++) {
                float* cc = c[mi][nj * 2 + jj];
                int gm = m0 + wm + mi * 16 + (lane >> 2);
                int gn = n0 + wn + nj * 16 + jj * 8 + (lane & 3) * 2;
                put(gm,     gn,     cc[0], rsum[mi][0]);
                put(gm,     gn + 1, cc[1], rsum[mi][0]);
                put(gm + 8, gn,     cc[2], rsum[mi][1]);
                put(gm + 8, gn + 1, cc[3], rsum[mi][1]);
            }
#pragma unroll
    for (int mi = 0; mi < 2; mi++)
#pragma unroll
        for (int rr = 0; rr < 2; rr++) {
            float v = rsum[mi][rr];
            v += __shfl_xor_sync(0xffffffffu, v, 1);
            v += __shfl_xor_sync(0xffffffffu, v, 2);
            if ((lane & 3) == 0) {
                int gm = m0 + wm + mi * 16 + (lane >> 2) + rr * 8;
                if (gm < N_ANCH) atomicAdd(&Srow[gm], v);
            }
        }
}

// ---------------- K5: Z^T (fp8*4096) and U (bf16):  baf @ [W3a;W3b]^T ----------------
__global__ __launch_bounds__(256) void k_zu() {
    const int S = DFEAT / 16;   // 44
    int b  = blockIdx.z;
    int m0 = blockIdx.y * 128;
    const __nv_bfloat16* A_g = g_baf + (size_t)b * N_ANCH * DFEAT;
    unsigned char* Zt = g_Zt8 + (size_t)b * 80 * N_ANCH;
    __nv_bfloat16* U  = g_U   + (size_t)b * N_ANCH * 80;

    __shared__ __align__(16) __nv_bfloat16 sA[2][128][24];
    __shared__ __align__(16) __nv_bfloat16 sB[2][160][24];

    int tid = threadIdx.x, lane = tid & 31, warp = tid >> 5;
    int wm = warp * 16;
    float c[20][4] = {};

    auto load_stage = [&](int st, int s) {
        int k = s * 16;
        {
            int row = tid >> 1, seg = tid & 1;
            int gm = m0 + row; bool ok = gm < N_ANCH;
            cpa16(sptr(&sA[st][row][seg * 8]),
                  A_g + (size_t)(ok ? gm : 0) * DFEAT + k + seg * 8, ok);
        }
#pragma unroll
        for (int l = 0; l < 2; l++) {
            int idx = tid + l * 256;
            if (idx < 320) {
                int row = idx >> 1, seg = idx & 1;
                cpa16(sptr(&sB[st][row][seg * 8]),
                      g_wZU + (size_t)row * DFEAT + k + seg * 8, true);
            }
        }
    };

    load_stage(0, 0);
    cp_commit();

    int lr = lane & 15, lc = (lane >> 4) * 8;
    for (int s = 0; s < S; s++) {
        if (s + 1 < S) { load_stage((s + 1) & 1, s + 1); cp_commit(); }
        if (s + 1 < S) asm volatile("cp.async.wait_group 1;\n");
        else           asm volatile("cp.async.wait_group 0;\n");
        __syncthreads();
        int st = s & 1;
        uint32_t a[4];
        ldsm4(a, sptr(&sA[st][wm + lr][lc]));
#pragma unroll
        for (int nj = 0; nj < 10; nj++) {
            uint32_t bb[4];
            ldsm4(bb, sptr(&sB[st][nj * 16 + lr][lc]));
            mma16816(c[nj * 2 + 0], a, bb[0], bb[2]);
            mma16816(c[nj * 2 + 1], a, bb[1], bb[3]);
        }
        __syncthreads();
    }

#pragma unroll
    for (int nj = 0; nj < 10; nj++)
#pragma unroll
        for (int jj = 0; jj < 2; jj++) {
            float* cc = c[nj * 2 + jj];
            int col = nj * 16 + jj * 8 + (lane & 3) * 2;
            int gm0 = m0 + wm + (lane >> 2);
#pragma unroll
            for (int rr = 0; rr < 2; rr++) {
                int gm = gm0 + rr * 8;
                if (gm >= N_ANCH) continue;
                float v0 = cc[rr * 2 + 0], v1 = cc[rr * 2 + 1];
                if (col < 80) {
                    Zt[(size_t)col * N_ANCH + gm]       = to_fp8(v0 * SC_Z);
                    Zt[(size_t)(col + 1) * N_ANCH + gm] = to_fp8(v1 * SC_Z);
                } else {
                    *(__nv_bfloat162*)&U[(size_t)gm * 80 + (col - 80)] = pack2(v0, v1);
                }
            }
        }
}

// ---------------- K6 (fp8): out = (E @ Zt^T) / (4096*rowsum) + U + biases + anchors ----------------
#define OA_STG 10240u       // 128 rows * 80B
#define OB_STG 6400u        // 80 rows * 80B
#define SMEMO_TOT (NSTG * (OA_STG + OB_STG))   // 49920

__global__ __launch_bounds__(256, 2) void k_out(const float* __restrict__ cls_b,
                                                const float* __restrict__ reg_b,
                                                const float* __restrict__ anchors,
                                                float* __restrict__ out, int bz0) {
    const int Kvalid = N_ANCH;                  // 2784
    const int S = (Kvalid + 63) / 64;           // 44
    int b  = bz0 + blockIdx.z;
    int m0 = blockIdx.y * 128;
    const unsigned char* P  = g_s8  + (size_t)b * N_ANCH * N_ANCH;
    const unsigned char* Zt = g_Zt8 + (size_t)b * 80 * N_ANCH;
    const __nv_bfloat16* U  = g_U   + (size_t)b * N_ANCH * 80;
    const float* sums = g_sum + (size_t)b * N_ANCH;

    extern __shared__ __align__(16) char smem[];
    uint32_t sbA = sptr(smem);
    uint32_t sbB = sbA + NSTG * OA_STG;

    int tid = threadIdx.x, lane = tid & 31, warp = tid >> 5;
    int wm = warp * 16;
    float c[10][4] = {};

    auto load_stage = [&](int s, int buf) {
        int ks = s * 64;
        uint32_t baA = sbA + buf * OA_STG;
        uint32_t baB = sbB + buf * OB_STG;
#pragma unroll
        for (int i = 0; i < 2; i++) {
            int idx = tid + i * 256;
            int row = idx >> 2, ch = idx & 3;
            int koff = ks + ch * 16;
            bool okk = koff < Kvalid;
            int gm = m0 + row;
            bool okA = okk && (gm < N_ANCH);
            cpa16(baA + (uint32_t)row * 80u + (uint32_t)ch * 16u,
                  P + (size_t)(okA ? gm : 0) * N_ANCH + (okk ? koff : 0), okA);
        }
#pragma unroll
        for (int l = 0; l < 2; l++) {
            int idx = tid + l * 256;
            if (idx < 320) {
                int row = idx >> 2, ch = idx & 3;
                int koff = ks + ch * 16;
                bool okk = koff < Kvalid;
                cpa16(baB + (uint32_t)row * 80u + (uint32_t)ch * 16u,
                      Zt + (size_t)row * N_ANCH + (okk ? koff : 0), okk);
            }
        }
    };

#pragma unroll
    for (int s = 0; s < NSTG - 1; s++) { load_stage(s, s); cp_commit(); }

    int lr = lane & 15;
    uint32_t lcb = (uint32_t)(lane >> 4) * 16u;
    uint32_t aoffo = (uint32_t)(wm + lr) * 80u + lcb;
    uint32_t boffo[5];
#pragma unroll
    for (int nj = 0; nj < 5; nj++) boffo[nj] = (uint32_t)(nj * 16 + lr) * 80u + lcb;

    for (int s = 0; s < S; s++) {
        asm volatile("cp.async.wait_group %0;" :: "n"(NSTG - 2) : "memory");
        __syncthreads();
        int st = s % NSTG;
        uint32_t aA = sbA + (uint32_t)st * OA_STG;
        uint32_t aB = sbB + (uint32_t)st * OB_STG;
#pragma unroll
        for (int h = 0; h < 2; h++) {
            uint32_t cb = (uint32_t)h * 32u;
            uint32_t a[4];
            ldsm4(a, aA + aoffo + cb);
#pragma unroll
            for (int nj = 0; nj < 5; nj++) {
                uint32_t bb[4];
                ldsm4(bb, aB + boffo[nj] + cb);
                mma16832(c[nj * 2 + 0], a, bb[0], bb[2]);
                mma16832(c[nj * 2 + 1], a, bb[1], bb[3]);
            }
        }
        __syncthreads();
        int t = s + NSTG - 1;
        if (t < S) load_stage(t, t % NSTG);
        cp_commit();
    }

#pragma unroll
    for (int nj = 0; nj < 5; nj++)
#pragma unroll
        for (int jj = 0; jj < 2; jj++) {
            float* cc = c[nj * 2 + jj];
            int o = nj * 16 + jj * 8 + (lane & 3) * 2;
            int gm0 = m0 + wm + (lane >> 2);
#pragma unroll
            for (int rr = 0; rr < 2; rr++) {
                int gm = gm0 + rr * 8;
                if (gm >= N_ANCH) continue;
                float scl = INV_Z / __ldg(&sums[gm]);
                float* orow = out + ((size_t)(b * N_ANCH + gm)) * OUTW;
                const float* arow = anchors + (size_t)gm * OUTW;
#pragma unroll
                for (int e = 0; e < 2; e++) {
                    int oo = o + e;
                    if (oo >= RCOLS) continue;
                    float v = cc[rr * 2 + e] * scl
                            + __bfloat162float(U[(size_t)gm * 80 + oo]);
                    if (oo < 2) orow[oo] = v + cls_b[oo];
                    else { int col = oo + 2; orow[col] = v + reg_b[oo - 2] + arow[col]; }
                }
            }
        }
    {
        int r = tid >> 1, cs = tid & 1;
        int gm = m0 + r;
        if (gm < N_ANCH)
            out[((size_t)(b * N_ANCH + gm)) * OUTW + 2 + cs] = anchors[(size_t)gm * OUTW + 2 + cs];
    }
}

// ---------------- launch (fork + batch-pipelined tail) ----------------
extern "C" void kernel_launch(void* const* d_in, const int* in_sizes, int n_in,
                              void* d_out, int out_size) {
    const float* x        = (const float*)d_in[0];
    const float* conv1_w  = (const float*)d_in[1];
    const float* conv1_b  = (const float*)d_in[2];
    const float* attn_w   = (const float*)d_in[3];
    const float* attn_b   = (const float*)d_in[4];
    const float* cls_w    = (const float*)d_in[5];
    const float* cls_b    = (const float*)d_in[6];
    const float* reg_w    = (const float*)d_in[7];
    const float* reg_b    = (const float*)d_in[8];
    const float* anchors  = (const float*)d_in[9];
    const int*   cut_xs   = (const int*)d_in[10];
    const unsigned char* invalid = (const unsigned char*)d_in[11];
    float* out = (float*)d_out;

    static cudaStream_t s1 = nullptr;
    static cudaEvent_t evStart = nullptr, evGather = nullptr, evZU = nullptr,
                       evW = nullptr, evG0 = nullptr, evOutA = nullptr;
    if (!s1) {
        cudaFuncSetAttribute(k_gemm1_fp8, cudaFuncAttributeMaxDynamicSharedMemorySize, SMEM1_TOT);
        cudaFuncSetAttribute(k_out, cudaFuncAttributeMaxDynamicSharedMemorySize, SMEMO_TOT);
        cudaStreamCreateWithFlags(&s1, cudaStreamNonBlocking);
        cudaEventCreateWithFlags(&evStart,  cudaEventDisableTiming);
        cudaEventCreateWithFlags(&evGather, cudaEventDisableTiming);
        cudaEventCreateWithFlags(&evZU,     cudaEventDisableTiming);
        cudaEventCreateWithFlags(&evW,      cudaEventDisableTiming);
        cudaEventCreateWithFlags(&evG0,     cudaEventDisableTiming);
        cudaEventCreateWithFlags(&evOutA,   cudaEventDisableTiming);
    }

    cudaStream_t s0 = 0;   // harness-captured stream

    // main chain
    cudaEventRecord(evStart, s0);
    k_feat<<<BATCH * FH * FW, 64, 0, s0>>>(x, conv1_w, conv1_b);
    k_gather<<<dim3(N_ANCH, BATCH), 128, 0, s0>>>(cut_xs, invalid);
    cudaEventRecord(evGather, s0);

    // side branch: zero + convw + convwzu + zu
    cudaStreamWaitEvent(s1, evStart, 0);
    k_zero<<<(BATCH * N_ANCH + 255) / 256, 256, 0, s1>>>();
    k_convw<<<(NK * DFEAT + 255) / 256, 256, 0, s1>>>(attn_w);
    cudaEventRecord(evW, s1);
    k_convwzu<<<(160 * DFEAT + 255) / 256, 256, 0, s1>>>(cls_w, reg_w);
    cudaStreamWaitEvent(s1, evGather, 0);
    k_zu<<<dim3(1, 22, BATCH), 256, 0, s1>>>();
    cudaEventRecord(evZU, s1);

    // gemm1 first half (batches 0-3)
    cudaStreamWaitEvent(s0, evW, 0);
    k_gemm1_fp8<<<dim3(22, 22, 4), 256, SMEM1_TOT, s0>>>(attn_b, 0);
    cudaEventRecord(evG0, s0);

    // gemm1 second half (batches 4-7) on s0; k_out first half on s1 in parallel
    k_gemm1_fp8<<<dim3(22, 22, 4), 256, SMEM1_TOT, s0>>>(attn_b, 4);

    cudaStreamWaitEvent(s1, evG0, 0);   // s1 already ordered after evZU (zu on s1)
    k_out<<<dim3(1, 22, 4), 256, SMEMO_TOT, s1>>>(cls_b, reg_b, anchors, out, 0);
    cudaEventRecord(evOutA, s1);

    // k_out second half on s0 (after gemm1_B; needs zu)
    cudaStreamWaitEvent(s0, evZU, 0);
    k_out<<<dim3(1, 22, 4), 256, SMEMO_TOT, s0>>>(cls_b, reg_b, anchors, out, 4);

    // join side stream back into s0
    cudaStreamWaitEvent(s0, evOutA, 0);
}

// round 17
// speedup vs baseline: 1.0378x; 1.0378x over previous
#include <cuda_runtime.h>
#include <cuda_bf16.h>
#include <cuda_fp8.h>
#include <cstdint>

// ---------------- problem constants ----------------
#define BATCH   8
#define N_ANCH  2784
#define NK      2783
#define DFEAT   704
#define DCAT    1408
#define FH      11
#define FW      20
#define CB      512
#define CF      64
#define OUTW    77
#define RCOLS   75

// fp8 scales (powers of 2, exact)
#define SC_BAF   16.0f
#define SC_W     64.0f
#define INV_G1   (1.0f / (SC_BAF * SC_W))    // 1/1024
#define SC_P     256.0f                       // E storage scale
#define SC_Z     4096.0f                      // Z storage scale
#define INV_Z    (1.0f / SC_Z)                // 1/4096

// ---------------- scratch (device globals) ----------------
__device__ float g_feat[(size_t)BATCH * CF * FH * FW];
__device__ __nv_bfloat16 g_baf [(size_t)BATCH * N_ANCH * DFEAT];   // bf16 gathered
__device__ unsigned char g_baf8[(size_t)BATCH * N_ANCH * DFEAT];   // fp8 baf*16
__device__ unsigned char g_w8  [(size_t)NK * DFEAT];               // fp8 attn_w*64
__device__ unsigned char g_s8  [(size_t)BATCH * N_ANCH * N_ANCH];  // fp8 E=exp(score)*256, m-layout, diag=0
__device__ float         g_sum [(size_t)BATCH * N_ANCH];           // rowsum(exp)*256 (atomic)
__device__ __nv_bfloat16 g_wZU [(size_t)160 * DFEAT];              // [W3a(80); W3b(80)] rows x 704
__device__ unsigned char g_Zt8 [(size_t)BATCH * 80 * N_ANCH];      // fp8 Z^T * 4096
__device__ __nv_bfloat16 g_U   [(size_t)BATCH * N_ANCH * 80];      // U row-major bf16

// ---------------- helpers ----------------
__device__ __forceinline__ uint32_t sptr(const void* p) {
    return (uint32_t)__cvta_generic_to_shared(p);
}
__device__ __forceinline__ void cpa16(uint32_t dst, const void* src, bool ok) {
    int sz = ok ? 16 : 0;
    asm volatile("cp.async.cg.shared.global [%0], [%1], 16, %2;\n"
                 :: "r"(dst), "l"(src), "r"(sz));
}
__device__ __forceinline__ void cp_commit() { asm volatile("cp.async.commit_group;\n"); }
__device__ __forceinline__ void ldsm4(uint32_t* r, uint32_t a) {
    asm volatile("ldmatrix.sync.aligned.m8n8.x4.shared.b16 {%0,%1,%2,%3}, [%4];"
                 : "=r"(r[0]), "=r"(r[1]), "=r"(r[2]), "=r"(r[3]) : "r"(a));
}
__device__ __forceinline__ void mma16816(float* c, const uint32_t* a, uint32_t b0, uint32_t b1) {
    asm volatile("mma.sync.aligned.m16n8k16.row.col.f32.bf16.bf16.f32 "
                 "{%0,%1,%2,%3}, {%4,%5,%6,%7}, {%8,%9}, {%0,%1,%2,%3};"
                 : "+f"(c[0]), "+f"(c[1]), "+f"(c[2]), "+f"(c[3])
                 : "r"(a[0]), "r"(a[1]), "r"(a[2]), "r"(a[3]), "r"(b0), "r"(b1));
}
__device__ __forceinline__ void mma16832(float* c, const uint32_t* a, uint32_t b0, uint32_t b1) {
    asm volatile("mma.sync.aligned.m16n8k32.row.col.f32.e4m3.e4m3.f32 "
                 "{%0,%1,%2,%3}, {%4,%5,%6,%7}, {%8,%9}, {%0,%1,%2,%3};"
                 : "+f"(c[0]), "+f"(c[1]), "+f"(c[2]), "+f"(c[3])
                 : "r"(a[0]), "r"(a[1]), "r"(a[2]), "r"(a[3]), "r"(b0), "r"(b1));
}
__device__ __forceinline__ __nv_bfloat162 pack2(float a, float b) {
    return __floats2bfloat162_rn(a, b);
}
__device__ __forceinline__ unsigned char to_fp8(float v) {
    return (unsigned char)__nv_cvt_float_to_fp8(v, __NV_SATFINITE, __NV_E4M3);
}
__device__ __forceinline__ float fp8_to_f(unsigned char c) {
    __half_raw h = __nv_cvt_fp8_to_halfraw(c, __NV_E4M3);
    return __half2float(*(__half*)&h);
}

// ---------------- K0: zero rowsum accumulator ----------------
__global__ __launch_bounds__(256) void k_zero() {
    int i = blockIdx.x * 256 + threadIdx.x;
    if (i < BATCH * N_ANCH) g_sum[i] = 0.f;
}

// ---------------- K1: 1x1 conv ----------------
__global__ __launch_bounds__(64) void k_feat(const float* __restrict__ x,
                                             const float* __restrict__ w,
                                             const float* __restrict__ bias) {
    int p = blockIdx.x;
    int wpos = p % FW;
    int h = (p / FW) % FH;
    int b = p / (FW * FH);
    __shared__ float xv[CB];
    const float* xp = x + ((size_t)b * CB) * (FH * FW) + h * FW + wpos;
    for (int c = threadIdx.x; c < CB; c += 64) xv[c] = xp[(size_t)c * (FH * FW)];
    __syncthreads();
    int o = threadIdx.x;
    const float* wr = w + (size_t)o * CB;
    float acc = bias[o];
#pragma unroll 8
    for (int c = 0; c < CB; c++) acc += wr[c] * xv[c];
    g_feat[(((size_t)b * CF + o) * FH + h) * FW + wpos] = acc;
}

// ---------------- K2: gather baf -> bf16 + fp8 ----------------
__global__ __launch_bounds__(128) void k_gather(const int* __restrict__ cut_xs,
                                                const unsigned char* __restrict__ invalid) {
    int n = blockIdx.x, b = blockIdx.y;
    __shared__ int xs[FH];
    __shared__ unsigned char inv[FH];
    if (threadIdx.x < FH) {
        xs[threadIdx.x]  = cut_xs[n * FH + threadIdx.x];
        inv[threadIdx.x] = invalid[n * FH + threadIdx.x];
    }
    __syncthreads();
    size_t base = ((size_t)(b * N_ANCH + n)) * DFEAT;
    __nv_bfloat16* dst = g_baf + base;
    unsigned char* dst8 = g_baf8 + base;
    const float* fb = g_feat + (size_t)b * CF * FH * FW;
    for (int d = threadIdx.x; d < DFEAT; d += 128) {
        int c = d / FH, h = d - c * FH;
        float v = inv[h] ? 0.0f : fb[(c * FH + h) * FW + xs[h]];
        dst[d] = __float2bfloat16(v);
        dst8[d] = to_fp8(v * SC_BAF);
    }
}

// ---------------- K2b: attn_w -> fp8 *64 ----------------
__global__ __launch_bounds__(256) void k_convw(const float* __restrict__ w) {
    size_t i = (size_t)blockIdx.x * 256 + threadIdx.x;
    if (i < (size_t)NK * DFEAT) g_w8[i] = to_fp8(w[i] * SC_W);
}

// ---------------- K2c: split heads W into [W3a; W3b] rows x 704 (bf16) ----------------
__global__ __launch_bounds__(256) void k_convwzu(const float* __restrict__ cls_w,
                                                 const float* __restrict__ reg_w) {
    int i = blockIdx.x * 256 + threadIdx.x;
    if (i < 160 * DFEAT) {
        int row = i / DFEAT, k = i - row * DFEAT;
        int o = (row < 80) ? row : row - 80;
        int kc = (row < 80) ? k : k + DFEAT;
        float v = 0.f;
        if (o < 2)          v = cls_w[(size_t)o * DCAT + kc];
        else if (o < RCOLS) v = reg_w[(size_t)(o - 2) * DCAT + kc];
        g_wZU[i] = __float2bfloat16(v);
    }
}

// =================================================================
// GEMM1 (fp8): E = fp8(exp(score)*256) diag-skip layout + fused rowsum
// 128x128, BK=64, 4-stage ring, single barrier per stage
// =================================================================
#define NSTG1 4
#define STG 10240u
#define SMEM1_TOT (NSTG1 * 2 * STG)   // 81920

__global__ __launch_bounds__(256, 2) void k_gemm1_fp8(const float* __restrict__ bias) {
    const int Kvalid = DFEAT;
    const int S = (Kvalid + 63) / 64;   // 11
    int bz = blockIdx.z;
    int m0 = blockIdx.y * 128;
    int n0 = blockIdx.x * 128;
    const unsigned char* A = g_baf8 + (size_t)bz * N_ANCH * DFEAT;
    const unsigned char* B = g_w8;
    unsigned char* C = g_s8 + (size_t)bz * N_ANCH * N_ANCH;
    float* Srow = g_sum + (size_t)bz * N_ANCH;

    extern __shared__ __align__(16) char smem[];
    uint32_t sbA = sptr(smem);
    uint32_t sbB = sbA + NSTG1 * STG;

    int tid = threadIdx.x, lane = tid & 31, warp = tid >> 5;
    int wm = (warp >> 1) * 32, wn = (warp & 1) * 64;
    float c[2][8][4] = {};

    auto load_stage = [&](int s, int buf) {
        int ks = s * 64;
        uint32_t baA = sbA + buf * STG;
        uint32_t baB = sbB + buf * STG;
#pragma unroll
        for (int i = 0; i < 2; i++) {
            int idx = tid + i * 256;
            int row = idx >> 2, ch = idx & 3;
            int koff = ks + ch * 16;
            bool okk = koff < Kvalid;
            int gm = m0 + row;
            bool okA = okk && (gm < N_ANCH);
            cpa16(baA + (uint32_t)row * 80u + (uint32_t)ch * 16u,
                  A + (size_t)(okA ? gm : 0) * DFEAT + (okk ? koff : 0), okA);
            int gn = n0 + row;
            bool okB = okk && (gn < NK);
            cpa16(baB + (uint32_t)row * 80u + (uint32_t)ch * 16u,
                  B + (size_t)(okB ? gn : 0) * DFEAT + (okk ? koff : 0), okB);
        }
    };

#pragma unroll
    for (int s = 0; s < NSTG1 - 1; s++) { if (s < S) load_stage(s, s); cp_commit(); }

    int lr = lane & 15;
    uint32_t lcb = (uint32_t)(lane >> 4) * 16u;
    uint32_t aoff[2], boff[4];
#pragma unroll
    for (int mi = 0; mi < 2; mi++) aoff[mi] = (uint32_t)(wm + mi * 16 + lr) * 80u + lcb;
#pragma unroll
    for (int nj = 0; nj < 4; nj++) boff[nj] = (uint32_t)(wn + nj * 16 + lr) * 80u + lcb;

    for (int s = 0; s < S; s++) {
        asm volatile("cp.async.wait_group %0;" :: "n"(NSTG1 - 2) : "memory");
        __syncthreads();
        int st = s % NSTG1;
        uint32_t aA = sbA + (uint32_t)st * STG;
        uint32_t aB = sbB + (uint32_t)st * STG;
#pragma unroll
        for (int h = 0; h < 2; h++) {
            uint32_t cb = (uint32_t)h * 32u;
            uint32_t a[2][4], bb[4][4];
#pragma unroll
            for (int mi = 0; mi < 2; mi++) ldsm4(a[mi], aA + aoff[mi] + cb);
#pragma unroll
            for (int nj = 0; nj < 4; nj++) ldsm4(bb[nj], aB + boff[nj] + cb);
#pragma unroll
            for (int mi = 0; mi < 2; mi++)
#pragma unroll
                for (int nj = 0; nj < 4; nj++) {
                    mma16832(c[mi][nj * 2 + 0], a[mi], bb[nj][0], bb[nj][2]);
                    mma16832(c[mi][nj * 2 + 1], a[mi], bb[nj][1], bb[nj][3]);
                }
        }
        // no second barrier: buffer (s+NSTG1-1)%NSTG1 was last read in iter s-1,
        // fully retired before this iteration's top barrier.
        int t = s + NSTG1 - 1;
        if (t < S) load_stage(t, t % NSTG1);
        cp_commit();
    }

    float rsum[2][2] = {};
    auto put = [&](int r, int k, float acc, float& rs) {
        if (r >= N_ANCH || k >= NK) return;
        float score = acc * INV_G1 + __ldg(&bias[k]);
        float ex = __expf(score) * SC_P;
        rs += ex;
        int m = k + (k >= r);
        C[(size_t)r * N_ANCH + m] = to_fp8(ex);
        if (k == r) C[(size_t)r * N_ANCH + r] = 0;
        if (r == NK && k == NK - 1) C[(size_t)r * N_ANCH + NK] = 0;
    };
#pragma unroll
    for (int mi = 0; mi < 2; mi++)
#pragma unroll
        for (int nj = 0; nj < 4; nj++)
#pragma unroll
            for (int jj = 0; jj < 2; jj++) {
                float* cc = c[mi][nj * 2 + jj];
                int gm = m0 + wm + mi * 16 + (lane >> 2);
                int gn = n0 + wn + nj * 16 + jj * 8 + (lane & 3) * 2;
                put(gm,     gn,     cc[0], rsum[mi][0]);
                put(gm,     gn + 1, cc[1], rsum[mi][0]);
                put(gm + 8, gn,     cc[2], rsum[mi][1]);
                put(gm + 8, gn + 1, cc[3], rsum[mi][1]);
            }
#pragma unroll
    for (int mi = 0; mi < 2; mi++)
#pragma unroll
        for (int rr = 0; rr < 2; rr++) {
            float v = rsum[mi][rr];
            v += __shfl_xor_sync(0xffffffffu, v, 1);
            v += __shfl_xor_sync(0xffffffffu, v, 2);
            if ((lane & 3) == 0) {
                int gm = m0 + wm + mi * 16 + (lane >> 2) + rr * 8;
                if (gm < N_ANCH) atomicAdd(&Srow[gm], v);
            }
        }
}

// ---------------- K5: Z^T (fp8*4096) and U (bf16):  baf @ [W3a;W3b]^T ----------------
__global__ __launch_bounds__(256) void k_zu() {
    const int S = DFEAT / 16;   // 44
    int b  = blockIdx.z;
    int m0 = blockIdx.y * 128;
    const __nv_bfloat16* A_g = g_baf + (size_t)b * N_ANCH * DFEAT;
    unsigned char* Zt = g_Zt8 + (size_t)b * 80 * N_ANCH;
    __nv_bfloat16* U  = g_U   + (size_t)b * N_ANCH * 80;

    __shared__ __align__(16) __nv_bfloat16 sA[2][128][24];
    __shared__ __align__(16) __nv_bfloat16 sB[2][160][24];

    int tid = threadIdx.x, lane = tid & 31, warp = tid >> 5;
    int wm = warp * 16;
    float c[20][4] = {};

    auto load_stage = [&](int st, int s) {
        int k = s * 16;
        {
            int row = tid >> 1, seg = tid & 1;
            int gm = m0 + row; bool ok = gm < N_ANCH;
            cpa16(sptr(&sA[st][row][seg * 8]),
                  A_g + (size_t)(ok ? gm : 0) * DFEAT + k + seg * 8, ok);
        }
#pragma unroll
        for (int l = 0; l < 2; l++) {
            int idx = tid + l * 256;
            if (idx < 320) {
                int row = idx >> 1, seg = idx & 1;
                cpa16(sptr(&sB[st][row][seg * 8]),
                      g_wZU + (size_t)row * DFEAT + k + seg * 8, true);
            }
        }
    };

    load_stage(0, 0);
    cp_commit();

    int lr = lane & 15, lc = (lane >> 4) * 8;
    for (int s = 0; s < S; s++) {
        if (s + 1 < S) { load_stage((s + 1) & 1, s + 1); cp_commit(); }
        if (s + 1 < S) asm volatile("cp.async.wait_group 1;\n");
        else           asm volatile("cp.async.wait_group 0;\n");
        __syncthreads();
        int st = s & 1;
        uint32_t a[4];
        ldsm4(a, sptr(&sA[st][wm + lr][lc]));
#pragma unroll
        for (int nj = 0; nj < 10; nj++) {
            uint32_t bb[4];
            ldsm4(bb, sptr(&sB[st][nj * 16 + lr][lc]));
            mma16816(c[nj * 2 + 0], a, bb[0], bb[2]);
            mma16816(c[nj * 2 + 1], a, bb[1], bb[3]);
        }
        __syncthreads();
    }

#pragma unroll
    for (int nj = 0; nj < 10; nj++)
#pragma unroll
        for (int jj = 0; jj < 2; jj++) {
            float* cc = c[nj * 2 + jj];
            int col = nj * 16 + jj * 8 + (lane & 3) * 2;
            int gm0 = m0 + wm + (lane >> 2);
#pragma unroll
            for (int rr = 0; rr < 2; rr++) {
                int gm = gm0 + rr * 8;
                if (gm >= N_ANCH) continue;
                float v0 = cc[rr * 2 + 0], v1 = cc[rr * 2 + 1];
                if (col < 80) {
                    Zt[(size_t)col * N_ANCH + gm]       = to_fp8(v0 * SC_Z);
                    Zt[(size_t)(col + 1) * N_ANCH + gm] = to_fp8(v1 * SC_Z);
                } else {
                    *(__nv_bfloat162*)&U[(size_t)gm * 80 + (col - 80)] = pack2(v0, v1);
                }
            }
        }
}

// ---------------- K6 (fp8): out = (E @ Zt^T) / (4096*rowsum) + U + biases + anchors ----------------
#define NSTGO 4
#define OA_STG 10240u       // 128 rows * 80B
#define OB_STG 6400u        // 80 rows * 80B
#define SMEMO_TOT (NSTGO * (OA_STG + OB_STG))   // 66560

__global__ __launch_bounds__(256, 2) void k_out(const float* __restrict__ cls_b,
                                                const float* __restrict__ reg_b,
                                                const float* __restrict__ anchors,
                                                float* __restrict__ out) {
    const int Kvalid = N_ANCH;                  // 2784
    const int S = (Kvalid + 63) / 64;           // 44
    int b  = blockIdx.z;
    int m0 = blockIdx.y * 128;
    const unsigned char* P  = g_s8  + (size_t)b * N_ANCH * N_ANCH;
    const unsigned char* Zt = g_Zt8 + (size_t)b * 80 * N_ANCH;
    const __nv_bfloat16* U  = g_U   + (size_t)b * N_ANCH * 80;
    const float* sums = g_sum + (size_t)b * N_ANCH;

    extern __shared__ __align__(16) char smem[];
    uint32_t sbA = sptr(smem);
    uint32_t sbB = sbA + NSTGO * OA_STG;

    int tid = threadIdx.x, lane = tid & 31, warp = tid >> 5;
    int wm = warp * 16;
    float c[10][4] = {};

    auto load_stage = [&](int s, int buf) {
        int ks = s * 64;
        uint32_t baA = sbA + buf * OA_STG;
        uint32_t baB = sbB + buf * OB_STG;
#pragma unroll
        for (int i = 0; i < 2; i++) {
            int idx = tid + i * 256;
            int row = idx >> 2, ch = idx & 3;
            int koff = ks + ch * 16;
            bool okk = koff < Kvalid;
            int gm = m0 + row;
            bool okA = okk && (gm < N_ANCH);
            cpa16(baA + (uint32_t)row * 80u + (uint32_t)ch * 16u,
                  P + (size_t)(okA ? gm : 0) * N_ANCH + (okk ? koff : 0), okA);
        }
#pragma unroll
        for (int l = 0; l < 2; l++) {
            int idx = tid + l * 256;
            if (idx < 320) {
                int row = idx >> 2, ch = idx & 3;
                int koff = ks + ch * 16;
                bool okk = koff < Kvalid;
                cpa16(baB + (uint32_t)row * 80u + (uint32_t)ch * 16u,
                      Zt + (size_t)row * N_ANCH + (okk ? koff : 0), okk);
            }
        }
    };

#pragma unroll
    for (int s = 0; s < NSTGO - 1; s++) { load_stage(s, s); cp_commit(); }

    int lr = lane & 15;
    uint32_t lcb = (uint32_t)(lane >> 4) * 16u;
    uint32_t aoffo = (uint32_t)(wm + lr) * 80u + lcb;
    uint32_t boffo[5];
#pragma unroll
    for (int nj = 0; nj < 5; nj++) boffo[nj] = (uint32_t)(nj * 16 + lr) * 80u + lcb;

    for (int s = 0; s < S; s++) {
        asm volatile("cp.async.wait_group %0;" :: "n"(NSTGO - 2) : "memory");
        __syncthreads();
        int st = s % NSTGO;
        uint32_t aA = sbA + (uint32_t)st * OA_STG;
        uint32_t aB = sbB + (uint32_t)st * OB_STG;
#pragma unroll
        for (int h = 0; h < 2; h++) {
            uint32_t cb = (uint32_t)h * 32u;
            uint32_t a[4];
            ldsm4(a, aA + aoffo + cb);
#pragma unroll
            for (int nj = 0; nj < 5; nj++) {
                uint32_t bb[4];
                ldsm4(bb, aB + boffo[nj] + cb);
                mma16832(c[nj * 2 + 0], a, bb[0], bb[2]);
                mma16832(c[nj * 2 + 1], a, bb[1], bb[3]);
            }
        }
        // no second barrier (same argument as gemm1)
        int t = s + NSTGO - 1;
        if (t < S) load_stage(t, t % NSTGO);
        cp_commit();
    }

#pragma unroll
    for (int nj = 0; nj < 5; nj++)
#pragma unroll
        for (int jj = 0; jj < 2; jj++) {
            float* cc = c[nj * 2 + jj];
            int o = nj * 16 + jj * 8 + (lane & 3) * 2;
            int gm0 = m0 + wm + (lane >> 2);
#pragma unroll
            for (int rr = 0; rr < 2; rr++) {
                int gm = gm0 + rr * 8;
                if (gm >= N_ANCH) continue;
                float scl = INV_Z / __ldg(&sums[gm]);
                float* orow = out + ((size_t)(b * N_ANCH + gm)) * OUTW;
                const float* arow = anchors + (size_t)gm * OUTW;
#pragma unroll
                for (int e = 0; e < 2; e++) {
                    int oo = o + e;
                    if (oo >= RCOLS) continue;
                    float v = cc[rr * 2 + e] * scl
                            + __bfloat162float(U[(size_t)gm * 80 + oo]);
                    if (oo < 2) orow[oo] = v + cls_b[oo];
                    else { int col = oo + 2; orow[col] = v + reg_b[oo - 2] + arow[col]; }
                }
            }
        }
    {
        int r = tid >> 1, cs = tid & 1;
        int gm = m0 + r;
        if (gm < N_ANCH)
            out[((size_t)(b * N_ANCH + gm)) * OUTW + 2 + cs] = anchors[(size_t)gm * OUTW + 2 + cs];
    }
}

// ---------------- launch (fork side-branch) ----------------
extern "C" void kernel_launch(void* const* d_in, const int* in_sizes, int n_in,
                              void* d_out, int out_size) {
    const float* x        = (const float*)d_in[0];
    const float* conv1_w  = (const float*)d_in[1];
    const float* conv1_b  = (const float*)d_in[2];
    const float* attn_w   = (const float*)d_in[3];
    const float* attn_b   = (const float*)d_in[4];
    const float* cls_w    = (const float*)d_in[5];
    const float* cls_b    = (const float*)d_in[6];
    const float* reg_w    = (const float*)d_in[7];
    const float* reg_b    = (const float*)d_in[8];
    const float* anchors  = (const float*)d_in[9];
    const int*   cut_xs   = (const int*)d_in[10];
    const unsigned char* invalid = (const unsigned char*)d_in[11];
    float* out = (float*)d_out;

    static cudaStream_t s1 = nullptr;
    static cudaEvent_t evStart = nullptr, evGather = nullptr, evZU = nullptr, evW = nullptr;
    if (!s1) {
        cudaFuncSetAttribute(k_gemm1_fp8, cudaFuncAttributeMaxDynamicSharedMemorySize, SMEM1_TOT);
        cudaFuncSetAttribute(k_out, cudaFuncAttributeMaxDynamicSharedMemorySize, SMEMO_TOT);
        cudaStreamCreateWithFlags(&s1, cudaStreamNonBlocking);
        cudaEventCreateWithFlags(&evStart,  cudaEventDisableTiming);
        cudaEventCreateWithFlags(&evGather, cudaEventDisableTiming);
        cudaEventCreateWithFlags(&evZU,     cudaEventDisableTiming);
        cudaEventCreateWithFlags(&evW,      cudaEventDisableTiming);
    }

    cudaStream_t s0 = 0;   // harness-captured stream

    // main chain
    cudaEventRecord(evStart, s0);
    k_feat<<<BATCH * FH * FW, 64, 0, s0>>>(x, conv1_w, conv1_b);
    k_gather<<<dim3(N_ANCH, BATCH), 128, 0, s0>>>(cut_xs, invalid);
    cudaEventRecord(evGather, s0);

    // side branch: zero + convw + convwzu + zu
    cudaStreamWaitEvent(s1, evStart, 0);
    k_zero<<<(BATCH * N_ANCH + 255) / 256, 256, 0, s1>>>();
    k_convw<<<(NK * DFEAT + 255) / 256, 256, 0, s1>>>(attn_w);
    cudaEventRecord(evW, s1);
    k_convwzu<<<(160 * DFEAT + 255) / 256, 256, 0, s1>>>(cls_w, reg_w);
    cudaStreamWaitEvent(s1, evGather, 0);
    k_zu<<<dim3(1, 22, BATCH), 256, 0, s1>>>();
    cudaEventRecord(evZU, s1);

    // main chain: gemm1 (writes E + rowsums)
    cudaStreamWaitEvent(s0, evW, 0);
    k_gemm1_fp8<<<dim3(22, 22, BATCH), 256, SMEM1_TOT, s0>>>(attn_b);

    // join: k_out needs gemm1 (s0) + zu (s1)
    cudaStreamWaitEvent(s0, evZU, 0);
    k_out<<<dim3(1, 22, BATCH), 256, SMEMO_TOT, s0>>>(cls_b, reg_b, anchors, out);
}